// round 14
// baseline (speedup 1.0000x reference)
#include <cuda_runtime.h>
#include <cuda_fp16.h>
#include <cstdint>
#include <cstddef>

#define BQ 512
#define TT 256
#define FF 128
#define HH 512
#define G4H 2048
#define BH (BQ*HH)

// ---------------- static device buffers ----------------
__device__ __align__(256) __half g_X16[(size_t)TT*BQ*FF];     // x fp16 [T][B][F]
__device__ __align__(256) __half g_BhHi[(size_t)G4H*HH];      // enc W_hh fp16 (gate-interleaved)
__device__ __align__(256) __half g_BxHi[(size_t)G4H*FF];      // enc W_ih fp16
__device__ __align__(256) __half g_BdHi[(size_t)G4H*HH];      // dec fused W fp16
__device__ __align__(256) __half g_WoHi[(size_t)FF*HH];       // Wo hi
__device__ __align__(256) __half g_WoLo[(size_t)FF*HH];       // Wo lo*2048
__device__ __align__(256) __half g_A16[2][(size_t)BQ*HH];     // enc h ping-pong fp16
__device__ __align__(256) __half g_hstore16[(size_t)TT*BH];   // fp16 h chain
__device__ __align__(256) float g_bencI[G4H];
__device__ __align__(256) float g_beffI[G4H];
__device__ unsigned g_flags[8];                               // per-chunk-group dataflow counters

// ---------------- helpers ----------------
__device__ __forceinline__ uint32_t smem_u32(const void* p){
  uint32_t a;
  asm("{ .reg .u64 t; cvta.to.shared.u64 t, %1; cvt.u32.u64 %0, t; }" : "=r"(a) : "l"(p));
  return a;
}
#define CP16(s,g)  asm volatile("cp.async.cg.shared.global [%0], [%1], 16;" :: "r"(s), "l"(g))
#define CPCOMMIT() asm volatile("cp.async.commit_group;" ::: "memory")
#define CPWAIT1()  asm volatile("cp.async.wait_group 1;" ::: "memory")

__device__ __forceinline__ float fast_tanh(float x){
  float r; asm("tanh.approx.f32 %0, %1;" : "=f"(r) : "f"(x)); return r;
}
__device__ __forceinline__ float fast_sig(float x){
  return 0.5f*fast_tanh(0.5f*x) + 0.5f;
}

#define PITCH    144
#define A_BYTES  (128*PITCH)               // 18432
#define BHI_OFF  A_BYTES
#define R_STAGE  (A_BYTES + 64*PITCH)      // 27648
#define R_SMEM   (6*R_STAGE + 512)         // stages + bias corner = 166400
#define GATE_OFF (2*R_STAGE)               // gates alias stages 2..4
#define GPITCH   68
#define GSM1_OFF (128*GPITCH*4)            // 34816
// out-gemm stage: A(128) + WoHi(64) + WoLo(64)
#define O_BLO_OFF (A_BYTES + 64*PITCH)
#define O_STAGE  (A_BYTES + 2*64*PITCH)    // 36864
#define O_SMEM   (6*O_STAGE)               // 221184

// ============================================================
// Persistent LSTM. Grid (4,32)=128 CTAs, 512 threads, 16 warps.
// CTA tile M=128 batch x N=64 gate cols (16 units). Warp w,w+8 share
// m32n32; kk-split. 6-stage ring, paired chunks, one sync/interval.
// NO global barrier: dataflow flags. A-chunk c (units 64c..64c+63)
// is produced by CTAs ny in [4c,4c+4) (x4 bx = 16 CTAs). After its
// epilogue each CTA bumps flags[ny>>2]; before loading chunk c a
// consumer spins flags[c] >= step*16. Consuming a full step requires
// all 8 groups = all 128 CTAs done with the previous step, so the
// ping-pong write-after-read hazard cannot occur; waits are acyclic
// in step order => deadlock-free. c-state lives in registers (CTA
// tile constant across steps); biases live in a smem corner.
// ============================================================
__global__ __launch_bounds__(512) void lstm_persistent(){
  extern __shared__ __align__(16) char smem[];
  const uint32_t sb = smem_u32(smem);
  float* sbias = reinterpret_cast<float*>(smem + 6*R_STAGE);  // [0..63] enc, [64..127] dec
  const int tid  = threadIdx.x;
  const int lane = tid & 31, warp = tid >> 5;
  const int wg = warp >> 3, w8 = warp & 7;
  const int wm = w8 >> 1, wn = w8 & 1;
  const int bBase = blockIdx.x * 128;
  const int nBase = blockIdx.y * 64;

  const int laA = (((lane >> 3) & 1) << 3) + (lane & 7);
  const int kaA = (lane >> 4) << 3;
  const int laB = ((lane >> 4) << 3) + (lane & 7);
  const int kaB = ((lane >> 3) & 1) << 3;

  // preload biases for this CTA's 64 gate cols
  if (tid < 64)        sbias[tid]      = g_bencI[nBase + tid];
  else if (tid < 128)  sbias[tid]      = g_beffI[nBase + (tid - 64)];
  __syncthreads();

  auto stage_of = [&](int c){ return sb + (uint32_t)(c % 6)*R_STAGE; };

  auto load_Bc = [&](int c, const __half* Bhp, int strB, int kb){
    uint32_t s0 = stage_of(c);
    int r = tid >> 3, q = tid & 7;
    CP16(s0 + BHI_OFF + r*PITCH + q*16, Bhp + (size_t)(nBase + r)*strB + kb + q*8);
  };
  auto load_Ac = [&](int c, const __half* As, int strA, int kb){
    uint32_t s0 = stage_of(c);
    #pragma unroll
    for (int i = 0; i < 2; i++){
      int ci = tid + 512*i;
      int r = ci >> 3, q = ci & 7;
      CP16(s0 + r*PITCH + q*16, As + (size_t)(bBase + r)*strA + kb + q*8);
    }
  };
  auto spin_flag = [&](int c, unsigned tgt){
    volatile unsigned* f = &g_flags[c];
    if (*f < tgt){ while (*f < tgt) __nanosleep(32); }
  };

  // kernel start: B of step-0 pair 0
  load_Bc(0, g_BhHi, HH, 0);
  load_Bc(1, g_BhHi, HH, 64);
  CPCOMMIT();

  // c-state registers: thread owns (bl = tid>>2, units uq*4..uq*4+3)
  const int bl = tid >> 2, uq = tid & 3;
  float creg[4] = {0.f, 0.f, 0.f, 0.f};

  for (int step = 0; step < 2*TT - 1; ++step){
    const bool enc = step < TT;
    const int  di  = step - TT;
    const int  NIT = enc ? 10 : 8;
    const int  NJ  = NIT >> 1;
    const unsigned tgt = (unsigned)step * 16u;
    const __half* Ain  = enc ? &g_A16[step & 1][0] : (g_hstore16 + (size_t)di*BH);
    __half*       Aout = enc ? ((step == TT-1) ? g_hstore16 : &g_A16[(step+1) & 1][0])
                             : (g_hstore16 + (size_t)(di + 1)*BH);
    const __half* Xp   = enc ? (g_X16 + (size_t)step*BQ*FF) : (const __half*)nullptr;
    const __half* Bhi  = enc ? g_BhHi : g_BdHi;
    const bool resetC = (step == TT-1);

    auto load_full = [&](int c){
      if (enc && c >= 8){
        load_Ac(c, Xp, FF, (c-8)*64);
        load_Bc(c, g_BxHi, FF, (c-8)*64);
      } else {
        spin_flag(c, tgt);
        load_Ac(c, Ain, HH, c*64);
        load_Bc(c, Bhi, HH, c*64);
      }
    };

    // prologue: A of pair 0 (B already in flight); full pair 1
    spin_flag(0, tgt); load_Ac(0, Ain, HH, 0);
    spin_flag(1, tgt); load_Ac(1, Ain, HH, 64);
    CPCOMMIT();
    load_full(2); load_full(3);
    CPCOMMIT();

    float accA[2][4][4];
    #pragma unroll
    for (int i=0;i<2;i++)
      #pragma unroll
      for (int j=0;j<4;j++)
        #pragma unroll
        for (int k=0;k<4;k++) accA[i][j][k]=0.f;

    auto compute_chunk = [&](int c){
      const uint32_t s0 = stage_of(c);
      #pragma unroll
      for (int kk2 = 0; kk2 < 2; kk2++){
        const int kk = wg*2 + kk2;
        uint32_t af[2][4];
        #pragma unroll
        for (int mi = 0; mi < 2; mi++){
          uint32_t ad = s0 + (uint32_t)((wm*32 + mi*16 + laA)*PITCH + (kk*16 + kaA)*2);
          asm volatile("ldmatrix.sync.aligned.m8n8.x4.shared.b16 {%0,%1,%2,%3}, [%4];"
            : "=r"(af[mi][0]),"=r"(af[mi][1]),"=r"(af[mi][2]),"=r"(af[mi][3]) : "r"(ad));
        }
        uint32_t bf[4][2];
        #pragma unroll
        for (int nj = 0; nj < 2; nj++){
          uint32_t bd = s0 + BHI_OFF + (uint32_t)((wn*32 + nj*16 + laB)*PITCH + (kk*16 + kaB)*2);
          uint32_t r0,r1,r2,r3;
          asm volatile("ldmatrix.sync.aligned.m8n8.x4.shared.b16 {%0,%1,%2,%3}, [%4];"
            : "=r"(r0),"=r"(r1),"=r"(r2),"=r"(r3) : "r"(bd));
          bf[nj*2][0]=r0; bf[nj*2][1]=r1; bf[nj*2+1][0]=r2; bf[nj*2+1][1]=r3;
        }
        #pragma unroll
        for (int mi = 0; mi < 2; mi++)
          #pragma unroll
          for (int nj = 0; nj < 4; nj++)
            asm volatile("mma.sync.aligned.m16n8k16.row.col.f32.f16.f16.f32 "
              "{%0,%1,%2,%3}, {%4,%5,%6,%7}, {%8,%9}, {%0,%1,%2,%3};"
              : "+f"(accA[mi][nj][0]),"+f"(accA[mi][nj][1]),
                "+f"(accA[mi][nj][2]),"+f"(accA[mi][nj][3])
              : "r"(af[mi][0]),"r"(af[mi][1]),"r"(af[mi][2]),"r"(af[mi][3]),
                "r"(bf[nj][0]),"r"(bf[nj][1]));
      }
    };

    for (int j = 0; j < NJ; ++j){
      CPWAIT1();
      __syncthreads();
      const int c0 = 2*j + 4;
      if (c0     < NIT) load_full(c0);
      if (c0 + 1 < NIT) load_full(c0 + 1);
      CPCOMMIT();
      compute_chunk(2*j);
      compute_chunk(2*j + 1);
    }

    __syncthreads();           // all compute done; all stages reusable

    // prefetch NEXT step's B pair 0 (stages 0,1)
    if (step + 1 < 2*TT - 1){
      const __half* nBhi = (step + 1 < TT) ? g_BhHi : g_BdHi;
      load_Bc(0, nBhi, HH, 0);
      load_Bc(1, nBhi, HH, 64);
    }
    CPCOMMIT();

    // gate buffers alias stages 2..4
    float* gsm0 = reinterpret_cast<float*>(smem + GATE_OFF);
    float* gsm1 = reinterpret_cast<float*>(smem + GATE_OFF + GSM1_OFF);
    {
      float* gsm = wg ? gsm1 : gsm0;
      const int r0 = lane >> 2, c0 = (lane & 3) * 2;
      #pragma unroll
      for (int mi = 0; mi < 2; mi++)
        #pragma unroll
        for (int nj = 0; nj < 4; nj++){
          int row = wm*32 + mi*16 + r0;
          int col = wn*32 + nj*8 + c0;
          gsm[row*GPITCH + col]       = accA[mi][nj][0];
          gsm[row*GPITCH + col + 1]   = accA[mi][nj][1];
          gsm[(row+8)*GPITCH + col]   = accA[mi][nj][2];
          gsm[(row+8)*GPITCH + col+1] = accA[mi][nj][3];
        }
    }
    __syncthreads();

    // LSTM pointwise: thread = (bl, unit-quad uq); c in registers
    {
      const float4* g0 = reinterpret_cast<const float4*>(gsm0 + bl*GPITCH + uq*16);
      const float4* g1 = reinterpret_cast<const float4*>(gsm1 + bl*GPITCH + uq*16);
      const float4* bs = reinterpret_cast<const float4*>(sbias + (enc ? 0 : 64) + uq*16);
      __align__(8) __half hh[4];
      #pragma unroll
      for (int i = 0; i < 4; i++){
        float4 ga = g0[i], gb = g1[i], bb = bs[i];
        float gi = ga.x + gb.x + bb.x;
        float gf = ga.y + gb.y + bb.y;
        float gg = ga.z + gb.z + bb.z;
        float go = ga.w + gb.w + bb.w;
        float i_ = fast_sig(gi), f_ = fast_sig(gf);
        float g_ = fast_tanh(gg), o_ = fast_sig(go);
        float cn = f_*creg[i] + i_*g_;
        creg[i] = resetC ? 0.0f : cn;
        hh[i] = __float2half_rn(o_*fast_tanh(cn));
      }
      int u0 = (nBase >> 2) + uq*4;
      *reinterpret_cast<uint2*>(Aout + (size_t)(bBase + bl)*HH + u0) =
          *reinterpret_cast<const uint2*>(hh);
    }

    // ---- signal: this CTA's h slice (unit group ny>>2) is published ----
    __threadfence();
    __syncthreads();
    if (tid == 0) atomicAdd(&g_flags[blockIdx.y >> 2], 1u);
  }
}

// ============================================================
// HMMA output GEMM: Y[m][f] = hstore16[m].Wo[f] + bo[f], m = i*512+b,
// -> out[b][T-1-i][f]. Wo exact via hi + lo*2048 dual pass.
// Grid (512, 2), tile M=128 x N=64, K=512 (8 chunks, 4 intervals).
// ============================================================
__global__ __launch_bounds__(512) void out_gemm_mma(
    const float* __restrict__ bo, float* __restrict__ out)
{
  extern __shared__ __align__(16) char smem[];
  const uint32_t sb = smem_u32(smem);
  const int tid  = threadIdx.x;
  const int lane = tid & 31, warp = tid >> 5;
  const int wg = warp >> 3, w8 = warp & 7;
  const int wm = w8 >> 1, wn = w8 & 1;
  const int rowBase = blockIdx.x * 128;
  const int nBase = blockIdx.y * 64;

  const int laA = (((lane >> 3) & 1) << 3) + (lane & 7);
  const int kaA = (lane >> 4) << 3;
  const int laB = ((lane >> 4) << 3) + (lane & 7);
  const int kaB = ((lane >> 3) & 1) << 3;

  auto stage_of = [&](int c){ return sb + (uint32_t)(c % 6)*O_STAGE; };
  auto load_full = [&](int c){
    uint32_t s0 = stage_of(c);
    int kb = c*64;
    #pragma unroll
    for (int i = 0; i < 2; i++){
      int ci = tid + 512*i;
      int r = ci >> 3, q = ci & 7;
      CP16(s0 + r*PITCH + q*16, g_hstore16 + (size_t)(rowBase + r)*HH + kb + q*8);
    }
    int r = tid >> 3, q = tid & 7;
    CP16(s0 + BHI_OFF  + r*PITCH + q*16, g_WoHi + (size_t)(nBase + r)*HH + kb + q*8);
    CP16(s0 + O_BLO_OFF+ r*PITCH + q*16, g_WoLo + (size_t)(nBase + r)*HH + kb + q*8);
  };

  load_full(0); load_full(1); CPCOMMIT();
  load_full(2); load_full(3); CPCOMMIT();

  float accA[2][4][4], accB[2][4][4];
  #pragma unroll
  for (int i=0;i<2;i++)
    #pragma unroll
    for (int j=0;j<4;j++)
      #pragma unroll
      for (int k=0;k<4;k++){ accA[i][j][k]=0.f; accB[i][j][k]=0.f; }

  for (int j = 0; j < 4; ++j){
    CPWAIT1();
    __syncthreads();
    const int c0 = 2*j + 4;
    if (c0     < 8) load_full(c0);
    if (c0 + 1 < 8) load_full(c0 + 1);
    CPCOMMIT();
    #pragma unroll
    for (int cc = 0; cc < 2; cc++){
      const int c = 2*j + cc;
      const uint32_t s0 = stage_of(c);
      #pragma unroll
      for (int kk2 = 0; kk2 < 2; kk2++){
        const int kk = wg*2 + kk2;
        uint32_t af[2][4];
        #pragma unroll
        for (int mi = 0; mi < 2; mi++){
          uint32_t ad = s0 + (uint32_t)((wm*32 + mi*16 + laA)*PITCH + (kk*16 + kaA)*2);
          asm volatile("ldmatrix.sync.aligned.m8n8.x4.shared.b16 {%0,%1,%2,%3}, [%4];"
            : "=r"(af[mi][0]),"=r"(af[mi][1]),"=r"(af[mi][2]),"=r"(af[mi][3]) : "r"(ad));
        }
        #pragma unroll
        for (int pass = 0; pass < 2; pass++){
          const uint32_t sBb = s0 + (pass ? O_BLO_OFF : BHI_OFF);
          uint32_t bf[4][2];
          #pragma unroll
          for (int nj = 0; nj < 2; nj++){
            uint32_t bd = sBb + (uint32_t)((wn*32 + nj*16 + laB)*PITCH + (kk*16 + kaB)*2);
            uint32_t r0,r1,r2,r3;
            asm volatile("ldmatrix.sync.aligned.m8n8.x4.shared.b16 {%0,%1,%2,%3}, [%4];"
              : "=r"(r0),"=r"(r1),"=r"(r2),"=r"(r3) : "r"(bd));
            bf[nj*2][0]=r0; bf[nj*2][1]=r1; bf[nj*2+1][0]=r2; bf[nj*2+1][1]=r3;
          }
          float (*acc)[4][4] = pass ? accB : accA;
          #pragma unroll
          for (int mi = 0; mi < 2; mi++)
            #pragma unroll
            for (int nj = 0; nj < 4; nj++)
              asm volatile("mma.sync.aligned.m16n8k16.row.col.f32.f16.f16.f32 "
                "{%0,%1,%2,%3}, {%4,%5,%6,%7}, {%8,%9}, {%0,%1,%2,%3};"
                : "+f"(acc[mi][nj][0]),"+f"(acc[mi][nj][1]),
                  "+f"(acc[mi][nj][2]),"+f"(acc[mi][nj][3])
                : "r"(af[mi][0]),"r"(af[mi][1]),"r"(af[mi][2]),"r"(af[mi][3]),
                  "r"(bf[nj][0]),"r"(bf[nj][1]));
        }
      }
    }
  }

  __syncthreads();
  float* gsm0 = reinterpret_cast<float*>(smem);
  float* gsm1 = reinterpret_cast<float*>(smem + GSM1_OFF);
  {
    const float inv = 1.0f/2048.0f;
    float* gsm = wg ? gsm1 : gsm0;
    const int r0 = lane >> 2, c0 = (lane & 3) * 2;
    #pragma unroll
    for (int mi = 0; mi < 2; mi++)
      #pragma unroll
      for (int nj = 0; nj < 4; nj++){
        int row = wm*32 + mi*16 + r0;
        int col = wn*32 + nj*8 + c0;
        gsm[row*GPITCH + col]       = accA[mi][nj][0] + inv*accB[mi][nj][0];
        gsm[row*GPITCH + col + 1]   = accA[mi][nj][1] + inv*accB[mi][nj][1];
        gsm[(row+8)*GPITCH + col]   = accA[mi][nj][2] + inv*accB[mi][nj][2];
        gsm[(row+8)*GPITCH + col+1] = accA[mi][nj][3] + inv*accB[mi][nj][3];
      }
  }
  __syncthreads();

  #pragma unroll
  for (int j = 0; j < 16; j++){
    int idx = tid + 512*j;
    int col = idx & 63, rowl = idx >> 6;
    int m = rowBase + rowl;
    int i = m >> 9, b = m & 511;
    int f = nBase + col;
    float y = gsm0[rowl*GPITCH + col] + gsm1[rowl*GPITCH + col] + bo[f];
    out[((size_t)b*TT + (TT - 1 - i))*FF + f] = y;
  }
}

// ============================================================
// prep kernels
// ============================================================
__global__ __launch_bounds__(128) void prep_x(const float* __restrict__ ts){
  int b = blockIdx.x, t = blockIdx.y, f = threadIdx.x;
  float v = ts[((size_t)b*TT + t)*FF + f];
  g_X16[((size_t)t*BQ + b)*FF + f] = __float2half_rn(v);
}

__global__ __launch_bounds__(128) void prep_wenc(
    const float* __restrict__ Wih, const float* __restrict__ Whh,
    const float* __restrict__ bih, const float* __restrict__ bhh)
{
  int r = blockIdx.x;
  int u = r >> 2, g = r & 3;
  size_t orig = (size_t)(g*HH + u);
  for (int c = threadIdx.x; c < HH; c += 128)
    g_BhHi[(size_t)r*HH + c] = __float2half_rn(Whh[orig*HH + c]);
  for (int c = threadIdx.x; c < FF; c += 128)
    g_BxHi[(size_t)r*FF + c] = __float2half_rn(Wih[orig*FF + c]);
  if (threadIdx.x == 0) g_bencI[r] = bih[orig] + bhh[orig];
}

__global__ __launch_bounds__(256) void prep_wdec(
    const float* __restrict__ dWih, const float* __restrict__ dWhh,
    const float* __restrict__ dbih, const float* __restrict__ dbhh,
    const float* __restrict__ Wo,   const float* __restrict__ bo)
{
  __shared__ float wih_s[FF];
  int r = blockIdx.x;
  int u = r >> 2, g = r & 3;
  size_t orig = (size_t)(g*HH + u);
  for (int k = threadIdx.x; k < FF; k += 256) wih_s[k] = dWih[orig*FF + k];
  __syncthreads();
  for (int c = threadIdx.x; c < HH; c += 256){
    float s = dWhh[orig*HH + c];
    #pragma unroll 8
    for (int k = 0; k < FF; k++) s += wih_s[k] * Wo[(size_t)k*HH + c];
    g_BdHi[(size_t)r*HH + c] = __float2half_rn(s);
  }
  if (threadIdx.x == 0){
    float bb = dbih[orig] + dbhh[orig];
    for (int k = 0; k < FF; k++) bb += wih_s[k] * bo[k];
    g_beffI[r] = bb;
  }
}

__global__ __launch_bounds__(128) void prep_wo(const float* __restrict__ Wo){
  int f = blockIdx.x;
  for (int c = threadIdx.x; c < HH; c += 128){
    float v = Wo[(size_t)f*HH + c];
    __half hi = __float2half_rn(v);
    g_WoHi[(size_t)f*HH + c] = hi;
    g_WoLo[(size_t)f*HH + c] = __float2half_rn((v - __half2float(hi)) * 2048.0f);
  }
}

// ============================================================
extern "C" void kernel_launch(void* const* d_in, const int* in_sizes, int n_in,
                              void* d_out, int out_size)
{
  const float* ts   = (const float*)d_in[0];
  const float* eWih = (const float*)d_in[1];
  const float* eWhh = (const float*)d_in[2];
  const float* ebih = (const float*)d_in[3];
  const float* ebhh = (const float*)d_in[4];
  const float* dWih = (const float*)d_in[5];
  const float* dWhh = (const float*)d_in[6];
  const float* dbih = (const float*)d_in[7];
  const float* dbhh = (const float*)d_in[8];
  const float* Wo   = (const float*)d_in[9];
  const float* bo   = (const float*)d_in[10];
  float* out = (float*)d_out;

  cudaFuncSetAttribute((const void*)lstm_persistent,
                       cudaFuncAttributeMaxDynamicSharedMemorySize, R_SMEM);
  cudaFuncSetAttribute((const void*)out_gemm_mma,
                       cudaFuncAttributeMaxDynamicSharedMemorySize, O_SMEM);

  __half *apA;
  unsigned *flA;
  cudaGetSymbolAddress((void**)&apA, g_A16);
  cudaGetSymbolAddress((void**)&flA, g_flags);

  // h0 = 0, flags = 0 (inside the graph, reset per replay)
  cudaMemsetAsync(apA, 0, (size_t)BQ*HH*sizeof(__half));
  cudaMemsetAsync(flA, 0, 8*sizeof(unsigned));

  prep_x   <<<dim3(BQ, TT), 128>>>(ts);
  prep_wenc<<<G4H, 128>>>(eWih, eWhh, ebih, ebhh);
  prep_wdec<<<G4H, 256>>>(dWih, dWhh, dbih, dbhh, Wo, bo);
  prep_wo  <<<FF, 128>>>(Wo);

  // ---- all 511 recurrent steps in one persistent kernel ----
  lstm_persistent<<<dim3(4, 32), 512, R_SMEM>>>();

  // ---- all outputs in one parallel HMMA GEMM, time-flipped write ----
  out_gemm_mma<<<dim3((TT*BQ)/128, FF/64), 512, O_SMEM>>>(bo, out);
}

// round 16
// speedup vs baseline: 1.2563x; 1.2563x over previous
#include <cuda_runtime.h>
#include <cuda_fp16.h>
#include <cstdint>
#include <cstddef>

#define BQ 512
#define TT 256
#define FF 128
#define HH 512
#define G4H 2048
#define BH (BQ*HH)

// ---------------- static device buffers ----------------
__device__ __align__(256) __half g_X16[(size_t)TT*BQ*FF];     // x fp16 [T][B][F]
__device__ __align__(256) __half g_BhHi[(size_t)G4H*HH];      // enc W_hh fp16 (gate-interleaved)
__device__ __align__(256) __half g_BxHi[(size_t)G4H*FF];      // enc W_ih fp16
__device__ __align__(256) __half g_BdHi[(size_t)G4H*HH];      // dec fused W fp16
__device__ __align__(256) __half g_WoHi[(size_t)FF*HH];       // Wo hi
__device__ __align__(256) __half g_WoLo[(size_t)FF*HH];       // Wo lo*2048
__device__ __align__(256) __half g_A16[2][(size_t)BQ*HH];     // enc h ping-pong fp16
__device__ __align__(256) __half g_hstore16[(size_t)TT*BH];   // fp16 h chain
__device__ __align__(256) float g_bencI[G4H];
__device__ __align__(256) float g_beffI[G4H];
__device__ unsigned g_gbar;                                   // grid barrier counter

// ---------------- helpers ----------------
__device__ __forceinline__ uint32_t smem_u32(const void* p){
  uint32_t a;
  asm("{ .reg .u64 t; cvta.to.shared.u64 t, %1; cvt.u32.u64 %0, t; }" : "=r"(a) : "l"(p));
  return a;
}
#define CP16(s,g)  asm volatile("cp.async.cg.shared.global [%0], [%1], 16;" :: "r"(s), "l"(g))
#define CPCOMMIT() asm volatile("cp.async.commit_group;" ::: "memory")
#define CPWAIT1()  asm volatile("cp.async.wait_group 1;" ::: "memory")

__device__ __forceinline__ float fast_tanh(float x){
  float r; asm("tanh.approx.f32 %0, %1;" : "=f"(r) : "f"(x)); return r;
}
__device__ __forceinline__ float fast_sig(float x){
  return 0.5f*fast_tanh(0.5f*x) + 0.5f;
}

#define PITCH    144
#define A_BYTES  (128*PITCH)               // 18432
#define BHI_OFF  A_BYTES
#define R_STAGE  (A_BYTES + 64*PITCH)      // 27648
#define R_SMEM   (6*R_STAGE + 512)         // stages + bias corner
#define GATE_OFF (2*R_STAGE)               // gates alias stages 2..4
#define GPITCH   68
#define GSM1_OFF (128*GPITCH*4)            // 34816
// out-gemm stage: A(128) + WoHi(64) + WoLo(64)
#define O_BLO_OFF (A_BYTES + 64*PITCH)
#define O_STAGE  (A_BYTES + 2*64*PITCH)    // 36864
#define O_SMEM   (6*O_STAGE)               // 221184

// ============================================================
// Persistent LSTM (R13 structure + register c-state).
// Grid (4,32)=128 CTAs, 512 threads, 16 warps.
// CTA tile M=128 batch x N=64 gate cols (16 units). Warp w,w+8 share
// m32n32; kk-split. 6-stage ring, paired chunks, one sync/interval:
//   interval j: wait_group 1; sync; load pair j+2; commit; compute 2j,2j+1
// Between steps: next step's B pair 0 prefetched before the grid
// barrier (single monotonic counter, 1 atomic + 1 poller per CTA).
// c-state lives in registers (thread's (batch,unit) tile fixed across
// steps); biases cached in a smem corner.
// ============================================================
__global__ __launch_bounds__(512) void lstm_persistent(){
  extern __shared__ __align__(16) char smem[];
  const uint32_t sb = smem_u32(smem);
  float* sbias = reinterpret_cast<float*>(smem + 6*R_STAGE);  // [0..63] enc, [64..127] dec
  const int tid  = threadIdx.x;
  const int lane = tid & 31, warp = tid >> 5;
  const int wg = warp >> 3, w8 = warp & 7;
  const int wm = w8 >> 1, wn = w8 & 1;
  const int bBase = blockIdx.x * 128;
  const int nBase = blockIdx.y * 64;

  const int laA = (((lane >> 3) & 1) << 3) + (lane & 7);
  const int kaA = (lane >> 4) << 3;
  const int laB = ((lane >> 4) << 3) + (lane & 7);
  const int kaB = ((lane >> 3) & 1) << 3;

  // preload biases for this CTA's 64 gate cols
  if (tid < 64)       sbias[tid] = g_bencI[nBase + tid];
  else if (tid < 128) sbias[tid] = g_beffI[nBase + (tid - 64)];
  __syncthreads();

  auto stage_of = [&](int c){ return sb + (uint32_t)(c % 6)*R_STAGE; };

  auto load_Bc = [&](int c, const __half* Bhp, int strB, int kb){
    uint32_t s0 = stage_of(c);
    int r = tid >> 3, q = tid & 7;
    CP16(s0 + BHI_OFF + r*PITCH + q*16, Bhp + (size_t)(nBase + r)*strB + kb + q*8);
  };
  auto load_Ac = [&](int c, const __half* As, int strA, int kb){
    uint32_t s0 = stage_of(c);
    #pragma unroll
    for (int i = 0; i < 2; i++){
      int ci = tid + 512*i;
      int r = ci >> 3, q = ci & 7;
      CP16(s0 + r*PITCH + q*16, As + (size_t)(bBase + r)*strA + kb + q*8);
    }
  };

  // kernel start: B of step-0 pair 0
  load_Bc(0, g_BhHi, HH, 0);
  load_Bc(1, g_BhHi, HH, 64);
  CPCOMMIT();

  // c-state registers: thread owns (bl = tid>>2, units uq*4..uq*4+3)
  const int bl = tid >> 2, uq = tid & 3;
  float creg[4] = {0.f, 0.f, 0.f, 0.f};
  unsigned barcnt = 0;

  for (int step = 0; step < 2*TT - 1; ++step){
    const bool enc = step < TT;
    const int  di  = step - TT;
    const int  NIT = enc ? 10 : 8;
    const int  NJ  = NIT >> 1;
    const __half* Ain  = enc ? &g_A16[step & 1][0] : (g_hstore16 + (size_t)di*BH);
    __half*       Aout = enc ? ((step == TT-1) ? g_hstore16 : &g_A16[(step+1) & 1][0])
                             : (g_hstore16 + (size_t)(di + 1)*BH);
    const __half* Xp   = enc ? (g_X16 + (size_t)step*BQ*FF) : (const __half*)nullptr;
    const __half* Bhi  = enc ? g_BhHi : g_BdHi;
    const bool resetC = (step == TT-1);

    auto load_full = [&](int c){
      if (enc && c >= 8){
        load_Ac(c, Xp, FF, (c-8)*64);
        load_Bc(c, g_BxHi, FF, (c-8)*64);
      } else {
        load_Ac(c, Ain, HH, c*64);
        load_Bc(c, Bhi, HH, c*64);
      }
    };

    // prologue: A of pair 0 (B already in flight); full pair 1
    load_Ac(0, Ain, HH, 0);
    load_Ac(1, Ain, HH, 64);
    CPCOMMIT();
    load_full(2); load_full(3);
    CPCOMMIT();

    float accA[2][4][4];
    #pragma unroll
    for (int i=0;i<2;i++)
      #pragma unroll
      for (int j=0;j<4;j++)
        #pragma unroll
        for (int k=0;k<4;k++) accA[i][j][k]=0.f;

    auto compute_chunk = [&](int c){
      const uint32_t s0 = stage_of(c);
      #pragma unroll
      for (int kk2 = 0; kk2 < 2; kk2++){
        const int kk = wg*2 + kk2;
        uint32_t af[2][4];
        #pragma unroll
        for (int mi = 0; mi < 2; mi++){
          uint32_t ad = s0 + (uint32_t)((wm*32 + mi*16 + laA)*PITCH + (kk*16 + kaA)*2);
          asm volatile("ldmatrix.sync.aligned.m8n8.x4.shared.b16 {%0,%1,%2,%3}, [%4];"
            : "=r"(af[mi][0]),"=r"(af[mi][1]),"=r"(af[mi][2]),"=r"(af[mi][3]) : "r"(ad));
        }
        uint32_t bf[4][2];
        #pragma unroll
        for (int nj = 0; nj < 2; nj++){
          uint32_t bd = s0 + BHI_OFF + (uint32_t)((wn*32 + nj*16 + laB)*PITCH + (kk*16 + kaB)*2);
          uint32_t r0,r1,r2,r3;
          asm volatile("ldmatrix.sync.aligned.m8n8.x4.shared.b16 {%0,%1,%2,%3}, [%4];"
            : "=r"(r0),"=r"(r1),"=r"(r2),"=r"(r3) : "r"(bd));
          bf[nj*2][0]=r0; bf[nj*2][1]=r1; bf[nj*2+1][0]=r2; bf[nj*2+1][1]=r3;
        }
        #pragma unroll
        for (int mi = 0; mi < 2; mi++)
          #pragma unroll
          for (int nj = 0; nj < 4; nj++)
            asm volatile("mma.sync.aligned.m16n8k16.row.col.f32.f16.f16.f32 "
              "{%0,%1,%2,%3}, {%4,%5,%6,%7}, {%8,%9}, {%0,%1,%2,%3};"
              : "+f"(accA[mi][nj][0]),"+f"(accA[mi][nj][1]),
                "+f"(accA[mi][nj][2]),"+f"(accA[mi][nj][3])
              : "r"(af[mi][0]),"r"(af[mi][1]),"r"(af[mi][2]),"r"(af[mi][3]),
                "r"(bf[nj][0]),"r"(bf[nj][1]));
      }
    };

    for (int j = 0; j < NJ; ++j){
      CPWAIT1();
      __syncthreads();
      const int c0 = 2*j + 4;
      if (c0     < NIT) load_full(c0);
      if (c0 + 1 < NIT) load_full(c0 + 1);
      CPCOMMIT();
      compute_chunk(2*j);
      compute_chunk(2*j + 1);
    }

    __syncthreads();           // all compute done; all stages reusable

    // prefetch NEXT step's B pair 0 (stages 0,1) before the grid barrier
    if (step + 1 < 2*TT - 1){
      const __half* nBhi = (step + 1 < TT) ? g_BhHi : g_BdHi;
      load_Bc(0, nBhi, HH, 0);
      load_Bc(1, nBhi, HH, 64);
    }
    CPCOMMIT();

    // gate buffers alias stages 2..4
    float* gsm0 = reinterpret_cast<float*>(smem + GATE_OFF);
    float* gsm1 = reinterpret_cast<float*>(smem + GATE_OFF + GSM1_OFF);
    {
      float* gsm = wg ? gsm1 : gsm0;
      const int r0 = lane >> 2, c0 = (lane & 3) * 2;
      #pragma unroll
      for (int mi = 0; mi < 2; mi++)
        #pragma unroll
        for (int nj = 0; nj < 4; nj++){
          int row = wm*32 + mi*16 + r0;
          int col = wn*32 + nj*8 + c0;
          gsm[row*GPITCH + col]       = accA[mi][nj][0];
          gsm[row*GPITCH + col + 1]   = accA[mi][nj][1];
          gsm[(row+8)*GPITCH + col]   = accA[mi][nj][2];
          gsm[(row+8)*GPITCH + col+1] = accA[mi][nj][3];
        }
    }
    __syncthreads();

    // LSTM pointwise: thread = (bl, unit-quad uq); c in registers
    {
      const float4* g0 = reinterpret_cast<const float4*>(gsm0 + bl*GPITCH + uq*16);
      const float4* g1 = reinterpret_cast<const float4*>(gsm1 + bl*GPITCH + uq*16);
      const float4* bs = reinterpret_cast<const float4*>(sbias + (enc ? 0 : 64) + uq*16);
      __align__(8) __half hh[4];
      #pragma unroll
      for (int i = 0; i < 4; i++){
        float4 ga = g0[i], gb = g1[i], bb = bs[i];
        float gi = ga.x + gb.x + bb.x;
        float gf = ga.y + gb.y + bb.y;
        float gg = ga.z + gb.z + bb.z;
        float go = ga.w + gb.w + bb.w;
        float i_ = fast_sig(gi), f_ = fast_sig(gf);
        float g_ = fast_tanh(gg), o_ = fast_sig(go);
        float cn = f_*creg[i] + i_*g_;
        creg[i] = resetC ? 0.0f : cn;
        hh[i] = __float2half_rn(o_*fast_tanh(cn));
      }
      int u0 = (nBase >> 2) + uq*4;
      *reinterpret_cast<uint2*>(Aout + (size_t)(bBase + bl)*HH + u0) =
          *reinterpret_cast<const uint2*>(hh);
    }

    // ---- grid barrier (monotonic counter) ----
    ++barcnt;
    __threadfence();
    __syncthreads();
    if (tid == 0){
      atomicAdd(&g_gbar, 1u);
      const unsigned target = barcnt * 128u;
      volatile unsigned* vp = &g_gbar;
      while (*vp < target) { }
      __threadfence();
    }
    __syncthreads();
  }
}

// ============================================================
// HMMA output GEMM: Y[m][f] = hstore16[m].Wo[f] + bo[f], m = i*512+b,
// -> out[b][T-1-i][f]. Wo exact via hi + lo*2048 dual pass.
// Grid (512, 2), tile M=128 x N=64, K=512 (8 chunks, 4 intervals).
// ============================================================
__global__ __launch_bounds__(512) void out_gemm_mma(
    const float* __restrict__ bo, float* __restrict__ out)
{
  extern __shared__ __align__(16) char smem[];
  const uint32_t sb = smem_u32(smem);
  const int tid  = threadIdx.x;
  const int lane = tid & 31, warp = tid >> 5;
  const int wg = warp >> 3, w8 = warp & 7;
  const int wm = w8 >> 1, wn = w8 & 1;
  const int rowBase = blockIdx.x * 128;
  const int nBase = blockIdx.y * 64;

  const int laA = (((lane >> 3) & 1) << 3) + (lane & 7);
  const int kaA = (lane >> 4) << 3;
  const int laB = ((lane >> 4) << 3) + (lane & 7);
  const int kaB = ((lane >> 3) & 1) << 3;

  auto stage_of = [&](int c){ return sb + (uint32_t)(c % 6)*O_STAGE; };
  auto load_full = [&](int c){
    uint32_t s0 = stage_of(c);
    int kb = c*64;
    #pragma unroll
    for (int i = 0; i < 2; i++){
      int ci = tid + 512*i;
      int r = ci >> 3, q = ci & 7;
      CP16(s0 + r*PITCH + q*16, g_hstore16 + (size_t)(rowBase + r)*HH + kb + q*8);
    }
    int r = tid >> 3, q = tid & 7;
    CP16(s0 + BHI_OFF  + r*PITCH + q*16, g_WoHi + (size_t)(nBase + r)*HH + kb + q*8);
    CP16(s0 + O_BLO_OFF+ r*PITCH + q*16, g_WoLo + (size_t)(nBase + r)*HH + kb + q*8);
  };

  load_full(0); load_full(1); CPCOMMIT();
  load_full(2); load_full(3); CPCOMMIT();

  float accA[2][4][4], accB[2][4][4];
  #pragma unroll
  for (int i=0;i<2;i++)
    #pragma unroll
    for (int j=0;j<4;j++)
      #pragma unroll
      for (int k=0;k<4;k++){ accA[i][j][k]=0.f; accB[i][j][k]=0.f; }

  for (int j = 0; j < 4; ++j){
    CPWAIT1();
    __syncthreads();
    const int c0 = 2*j + 4;
    if (c0     < 8) load_full(c0);
    if (c0 + 1 < 8) load_full(c0 + 1);
    CPCOMMIT();
    #pragma unroll
    for (int cc = 0; cc < 2; cc++){
      const int c = 2*j + cc;
      const uint32_t s0 = stage_of(c);
      #pragma unroll
      for (int kk2 = 0; kk2 < 2; kk2++){
        const int kk = wg*2 + kk2;
        uint32_t af[2][4];
        #pragma unroll
        for (int mi = 0; mi < 2; mi++){
          uint32_t ad = s0 + (uint32_t)((wm*32 + mi*16 + laA)*PITCH + (kk*16 + kaA)*2);
          asm volatile("ldmatrix.sync.aligned.m8n8.x4.shared.b16 {%0,%1,%2,%3}, [%4];"
            : "=r"(af[mi][0]),"=r"(af[mi][1]),"=r"(af[mi][2]),"=r"(af[mi][3]) : "r"(ad));
        }
        #pragma unroll
        for (int pass = 0; pass < 2; pass++){
          const uint32_t sBb = s0 + (pass ? O_BLO_OFF : BHI_OFF);
          uint32_t bf[4][2];
          #pragma unroll
          for (int nj = 0; nj < 2; nj++){
            uint32_t bd = sBb + (uint32_t)((wn*32 + nj*16 + laB)*PITCH + (kk*16 + kaB)*2);
            uint32_t r0,r1,r2,r3;
            asm volatile("ldmatrix.sync.aligned.m8n8.x4.shared.b16 {%0,%1,%2,%3}, [%4];"
              : "=r"(r0),"=r"(r1),"=r"(r2),"=r"(r3) : "r"(bd));
            bf[nj*2][0]=r0; bf[nj*2][1]=r1; bf[nj*2+1][0]=r2; bf[nj*2+1][1]=r3;
          }
          float (*acc)[4][4] = pass ? accB : accA;
          #pragma unroll
          for (int mi = 0; mi < 2; mi++)
            #pragma unroll
            for (int nj = 0; nj < 4; nj++)
              asm volatile("mma.sync.aligned.m16n8k16.row.col.f32.f16.f16.f32 "
                "{%0,%1,%2,%3}, {%4,%5,%6,%7}, {%8,%9}, {%0,%1,%2,%3};"
                : "+f"(acc[mi][nj][0]),"+f"(acc[mi][nj][1]),
                  "+f"(acc[mi][nj][2]),"+f"(acc[mi][nj][3])
                : "r"(af[mi][0]),"r"(af[mi][1]),"r"(af[mi][2]),"r"(af[mi][3]),
                  "r"(bf[nj][0]),"r"(bf[nj][1]));
        }
      }
    }
  }

  __syncthreads();
  float* gsm0 = reinterpret_cast<float*>(smem);
  float* gsm1 = reinterpret_cast<float*>(smem + GSM1_OFF);
  {
    const float inv = 1.0f/2048.0f;
    float* gsm = wg ? gsm1 : gsm0;
    const int r0 = lane >> 2, c0 = (lane & 3) * 2;
    #pragma unroll
    for (int mi = 0; mi < 2; mi++)
      #pragma unroll
      for (int nj = 0; nj < 4; nj++){
        int row = wm*32 + mi*16 + r0;
        int col = wn*32 + nj*8 + c0;
        gsm[row*GPITCH + col]       = accA[mi][nj][0] + inv*accB[mi][nj][0];
        gsm[row*GPITCH + col + 1]   = accA[mi][nj][1] + inv*accB[mi][nj][1];
        gsm[(row+8)*GPITCH + col]   = accA[mi][nj][2] + inv*accB[mi][nj][2];
        gsm[(row+8)*GPITCH + col+1] = accA[mi][nj][3] + inv*accB[mi][nj][3];
      }
  }
  __syncthreads();

  #pragma unroll
  for (int j = 0; j < 16; j++){
    int idx = tid + 512*j;
    int col = idx & 63, rowl = idx >> 6;
    int m = rowBase + rowl;
    int i = m >> 9, b = m & 511;
    int f = nBase + col;
    float y = gsm0[rowl*GPITCH + col] + gsm1[rowl*GPITCH + col] + bo[f];
    out[((size_t)b*TT + (TT - 1 - i))*FF + f] = y;
  }
}

// ============================================================
// prep kernels
// ============================================================
__global__ __launch_bounds__(128) void prep_x(const float* __restrict__ ts){
  int b = blockIdx.x, t0 = blockIdx.y * 16, f = threadIdx.x;
  #pragma unroll 4
  for (int dt = 0; dt < 16; dt++){
    int t = t0 + dt;
    float v = ts[((size_t)b*TT + t)*FF + f];
    g_X16[((size_t)t*BQ + b)*FF + f] = __float2half_rn(v);
  }
}

__global__ __launch_bounds__(128) void prep_wenc(
    const float* __restrict__ Wih, const float* __restrict__ Whh,
    const float* __restrict__ bih, const float* __restrict__ bhh)
{
  int r = blockIdx.x;
  int u = r >> 2, g = r & 3;
  size_t orig = (size_t)(g*HH + u);
  for (int c = threadIdx.x; c < HH; c += 128)
    g_BhHi[(size_t)r*HH + c] = __float2half_rn(Whh[orig*HH + c]);
  for (int c = threadIdx.x; c < FF; c += 128)
    g_BxHi[(size_t)r*FF + c] = __float2half_rn(Wih[orig*FF + c]);
  if (threadIdx.x == 0) g_bencI[r] = bih[orig] + bhh[orig];
}

__global__ __launch_bounds__(256) void prep_wdec(
    const float* __restrict__ dWih, const float* __restrict__ dWhh,
    const float* __restrict__ dbih, const float* __restrict__ dbhh,
    const float* __restrict__ Wo,   const float* __restrict__ bo)
{
  __shared__ float wih_s[FF];
  int r = blockIdx.x;
  int u = r >> 2, g = r & 3;
  size_t orig = (size_t)(g*HH + u);
  for (int k = threadIdx.x; k < FF; k += 256) wih_s[k] = dWih[orig*FF + k];
  __syncthreads();
  for (int c = threadIdx.x; c < HH; c += 256){
    float s = dWhh[orig*HH + c];
    #pragma unroll 8
    for (int k = 0; k < FF; k++) s += wih_s[k] * Wo[(size_t)k*HH + c];
    g_BdHi[(size_t)r*HH + c] = __float2half_rn(s);
  }
  if (threadIdx.x == 0){
    float bb = dbih[orig] + dbhh[orig];
    for (int k = 0; k < FF; k++) bb += wih_s[k] * bo[k];
    g_beffI[r] = bb;
  }
}

__global__ __launch_bounds__(128) void prep_wo(const float* __restrict__ Wo){
  int f = blockIdx.x;
  for (int c = threadIdx.x; c < HH; c += 128){
    float v = Wo[(size_t)f*HH + c];
    __half hi = __float2half_rn(v);
    g_WoHi[(size_t)f*HH + c] = hi;
    g_WoLo[(size_t)f*HH + c] = __float2half_rn((v - __half2float(hi)) * 2048.0f);
  }
}

// ============================================================
extern "C" void kernel_launch(void* const* d_in, const int* in_sizes, int n_in,
                              void* d_out, int out_size)
{
  const float* ts   = (const float*)d_in[0];
  const float* eWih = (const float*)d_in[1];
  const float* eWhh = (const float*)d_in[2];
  const float* ebih = (const float*)d_in[3];
  const float* ebhh = (const float*)d_in[4];
  const float* dWih = (const float*)d_in[5];
  const float* dWhh = (const float*)d_in[6];
  const float* dbih = (const float*)d_in[7];
  const float* dbhh = (const float*)d_in[8];
  const float* Wo   = (const float*)d_in[9];
  const float* bo   = (const float*)d_in[10];
  float* out = (float*)d_out;

  cudaFuncSetAttribute((const void*)lstm_persistent,
                       cudaFuncAttributeMaxDynamicSharedMemorySize, R_SMEM);
  cudaFuncSetAttribute((const void*)out_gemm_mma,
                       cudaFuncAttributeMaxDynamicSharedMemorySize, O_SMEM);

  __half *apA;
  unsigned *gbA;
  cudaGetSymbolAddress((void**)&apA, g_A16);
  cudaGetSymbolAddress((void**)&gbA, g_gbar);

  // h0 = 0, barrier counter = 0 (inside the graph, reset per replay)
  cudaMemsetAsync(apA, 0, (size_t)BQ*HH*sizeof(__half));
  cudaMemsetAsync(gbA, 0, sizeof(unsigned));

  prep_x   <<<dim3(BQ, TT/16), 128>>>(ts);
  prep_wenc<<<G4H, 128>>>(eWih, eWhh, ebih, ebhh);
  prep_wdec<<<G4H, 256>>>(dWih, dWhh, dbih, dbhh, Wo, bo);
  prep_wo  <<<FF, 128>>>(Wo);

  // ---- all 511 recurrent steps in one persistent kernel ----
  lstm_persistent<<<dim3(4, 32), 512, R_SMEM>>>();

  // ---- all outputs in one parallel HMMA GEMM, time-flipped write ----
  out_gemm_mma<<<dim3((TT*BQ)/128, FF/64), 512, O_SMEM>>>(bo, out);
}